// round 14
// baseline (speedup 1.0000x reference)
#include <cuda_runtime.h>
#include <cstdint>

// Haar wavelet transform, 14 levels, rows of 16384 fp32.
// cA = (even - odd) * INV_SQRT2 ; cD = (even + odd) * INV_SQRT2
// Output = concat over k=0..13 of cA_k ([nrows, 16384>>(k+1)]), then final cD ([nrows,1]).
//
// Converged structure (mixed-R/W HBM ceiling ~6.05 TB/s, floor ~84us):
//   - one 1024-thread block per row, grid = nrows
//   - Levels 0-3: thread-local registers (16 contiguous floats/thread, 4x LDG.128)
//   - Levels 4-8: in-warp via shfl (no barriers)
//   - Levels 9-13: warp 0 via shfl after ONE __syncthreads handoff through smem
//
// R14 experiment — completes the cache-policy matrix: DEFAULT reads (line is
// consumed by exactly one thread; policy should be neutral) + .cs STORES
// (evict-first dirty lines -> larger clean write bursts, fewer R/W turnarounds;
// the two best measured cells both had .cs stores).

#define ROW_LEN 16384
#define THREADS 1024

__global__ __launch_bounds__(THREADS, 2)
void haar14_kernel(const float* __restrict__ in, float* __restrict__ out, int nrows)
{
    __shared__ float sm[32];

    const int row  = blockIdx.x;
    const int t    = threadIdx.x;
    const int lane = t & 31;
    const int w    = t >> 5;
    const float S  = 0.70710678118654752440f;
    const unsigned FULL = 0xffffffffu;

    const float* rowp = in + (size_t)row * ROW_LEN;
    const size_t NR = (size_t)nrows;

    // ---- load 16 contiguous floats per thread (4x LDG.128, default policy) ----
    float v[16];
    {
        const float4* p4 = (const float4*)(rowp + t * 16);
        #pragma unroll
        for (int i = 0; i < 4; i++) {
            float4 f = p4[i];
            v[4*i+0] = f.x; v[4*i+1] = f.y; v[4*i+2] = f.z; v[4*i+3] = f.w;
        }
    }

    // ---- level 0: out length 8192 per row ----
    float d[8];
    {
        float a[8];
        #pragma unroll
        for (int i = 0; i < 8; i++) {
            float e = v[2*i], o = v[2*i+1];
            a[i] = (e - o) * S;
            d[i] = (e + o) * S;
        }
        float4* o4 = (float4*)(out + (size_t)row * 8192 + t * 8);
        __stcs(o4 + 0, make_float4(a[0], a[1], a[2], a[3]));
        __stcs(o4 + 1, make_float4(a[4], a[5], a[6], a[7]));
    }

    // ---- level 1: out length 4096 ----
    {
        float a[4];
        #pragma unroll
        for (int i = 0; i < 4; i++) {
            float e = d[2*i], o = d[2*i+1];
            a[i] = (e - o) * S;
            d[i] = (e + o) * S;
        }
        size_t base = NR * (size_t)(16384 - (16384 >> 1));
        float4* o4 = (float4*)(out + base + (size_t)row * 4096 + t * 4);
        __stcs(o4, make_float4(a[0], a[1], a[2], a[3]));
    }

    // ---- level 2: out length 2048 ----
    {
        float a[2];
        #pragma unroll
        for (int i = 0; i < 2; i++) {
            float e = d[2*i], o = d[2*i+1];
            a[i] = (e - o) * S;
            d[i] = (e + o) * S;
        }
        size_t base = NR * (size_t)(16384 - (16384 >> 2));
        float2* o2 = (float2*)(out + base + (size_t)row * 2048 + t * 2);
        __stcs(o2, make_float2(a[0], a[1]));
    }

    // ---- level 3: out length 1024 ----
    float val;   // surviving cD
    {
        float e = d[0], o = d[1];
        float a = (e - o) * S;
        val     = (e + o) * S;
        size_t base = NR * (size_t)(16384 - (16384 >> 3));
        __stcs(out + base + (size_t)row * 1024 + t, a);
    }

    // ---- levels 4..8: in-warp shuffles (32 -> 1 per warp) ----
    #pragma unroll
    for (int k = 4; k <= 8; k++) {
        const int m = 16384 >> (k + 1);           // per-row output length
        const int ml = 32 >> (k - 3);             // active lanes after this level
        float e = __shfl_sync(FULL, val, 2 * lane);
        float o = __shfl_sync(FULL, val, 2 * lane + 1);
        float a = (e - o) * S;
        val     = (e + o) * S;
        if (lane < ml) {
            size_t base = NR * (size_t)(16384 - (16384 >> k));
            __stcs(out + base + (size_t)row * m + w * ml + lane, a);
        }
    }
    // val at lane 0 of each warp = cD8[w]

    if (lane == 0) sm[w] = val;
    __syncthreads();

    // ---- levels 9..13 + final cD: warp 0 only ----
    if (w == 0) {
        val = sm[lane];   // 32 values: cD8[0..31]
        #pragma unroll
        for (int k = 9; k <= 13; k++) {
            const int m = 16384 >> (k + 1);       // 16,8,4,2,1
            float e = __shfl_sync(FULL, val, 2 * lane);
            float o = __shfl_sync(FULL, val, 2 * lane + 1);
            float a = (e - o) * S;
            val     = (e + o) * S;
            if (lane < m) {
                size_t base = NR * (size_t)(16384 - (16384 >> k));
                __stcs(out + base + (size_t)row * m + lane, a);
            }
        }
        if (lane == 0) {
            __stcs(out + NR * (size_t)16383 + row, val);   // final cD
        }
    }
}

extern "C" void kernel_launch(void* const* d_in, const int* in_sizes, int n_in,
                              void* d_out, int out_size)
{
    const float* x = (const float*)d_in[0];
    float* out = (float*)d_out;
    int n = in_sizes[0];
    int nrows = n / ROW_LEN;   // 4096 for (64,64,16384)
    haar14_kernel<<<nrows, THREADS>>>(x, out, nrows);
}

// round 15
// speedup vs baseline: 1.0057x; 1.0057x over previous
#include <cuda_runtime.h>
#include <cstdint>

// Haar wavelet transform, 14 levels, rows of 16384 fp32.
// cA = (even - odd) * INV_SQRT2 ; cD = (even + odd) * INV_SQRT2
// Output = concat over k=0..13 of cA_k ([nrows, 16384>>(k+1)]), then final cD ([nrows,1]).
//
// FINAL — converged at the mixed-R/W HBM-controller ceiling.
// Evidence: identical binary measures 83.58/84.03/84.58us (+/-1us noise);
// full cache-policy matrix spans 83.6-84.7 (indistinguishable); persistent CTAs
// 113us and deep-tile/low-occupancy 105us both regressed hard. 512 MB compulsory
// traffic / ~6.07 TB/s sustained mixed-stream bandwidth (76% of 8TB/s spec,
// standard R/W-turnaround derating) = ~84us floor. DRAM is the only saturated
// pipe (fma 15%, alu 15%, issue 30%); no reuse exists to exploit.
//
// Structure:
//   - one 1024-thread block per row, grid = nrows (block churn is free and
//     provides the latency slack persistence destroyed)
//   - Levels 0-3: thread-local registers (16 contiguous floats/thread, 4x LDG.128.CS)
//   - Levels 4-8: in-warp via shfl (no barriers)
//   - Levels 9-13: warp 0 via shfl after ONE __syncthreads handoff through smem
//   - both global streams use streaming (.cs) evict-first hints (nominal best)

#define ROW_LEN 16384
#define THREADS 1024

__global__ __launch_bounds__(THREADS, 2)
void haar14_kernel(const float* __restrict__ in, float* __restrict__ out, int nrows)
{
    __shared__ float sm[32];

    const int row  = blockIdx.x;
    const int t    = threadIdx.x;
    const int lane = t & 31;
    const int w    = t >> 5;
    const float S  = 0.70710678118654752440f;
    const unsigned FULL = 0xffffffffu;

    const float* rowp = in + (size_t)row * ROW_LEN;
    const size_t NR = (size_t)nrows;

    // ---- load 16 contiguous floats per thread (4x LDG.E.128.CS) ----
    float v[16];
    {
        const float4* p4 = (const float4*)(rowp + t * 16);
        #pragma unroll
        for (int i = 0; i < 4; i++) {
            float4 f = __ldcs(p4 + i);
            v[4*i+0] = f.x; v[4*i+1] = f.y; v[4*i+2] = f.z; v[4*i+3] = f.w;
        }
    }

    // ---- level 0: out length 8192 per row ----
    float d[8];
    {
        float a[8];
        #pragma unroll
        for (int i = 0; i < 8; i++) {
            float e = v[2*i], o = v[2*i+1];
            a[i] = (e - o) * S;
            d[i] = (e + o) * S;
        }
        float4* o4 = (float4*)(out + (size_t)row * 8192 + t * 8);
        __stcs(o4 + 0, make_float4(a[0], a[1], a[2], a[3]));
        __stcs(o4 + 1, make_float4(a[4], a[5], a[6], a[7]));
    }

    // ---- level 1: out length 4096 ----
    {
        float a[4];
        #pragma unroll
        for (int i = 0; i < 4; i++) {
            float e = d[2*i], o = d[2*i+1];
            a[i] = (e - o) * S;
            d[i] = (e + o) * S;
        }
        size_t base = NR * (size_t)(16384 - (16384 >> 1));
        float4* o4 = (float4*)(out + base + (size_t)row * 4096 + t * 4);
        __stcs(o4, make_float4(a[0], a[1], a[2], a[3]));
    }

    // ---- level 2: out length 2048 ----
    {
        float a[2];
        #pragma unroll
        for (int i = 0; i < 2; i++) {
            float e = d[2*i], o = d[2*i+1];
            a[i] = (e - o) * S;
            d[i] = (e + o) * S;
        }
        size_t base = NR * (size_t)(16384 - (16384 >> 2));
        float2* o2 = (float2*)(out + base + (size_t)row * 2048 + t * 2);
        __stcs(o2, make_float2(a[0], a[1]));
    }

    // ---- level 3: out length 1024 ----
    float val;   // surviving cD
    {
        float e = d[0], o = d[1];
        float a = (e - o) * S;
        val     = (e + o) * S;
        size_t base = NR * (size_t)(16384 - (16384 >> 3));
        __stcs(out + base + (size_t)row * 1024 + t, a);
    }

    // ---- levels 4..8: in-warp shuffles (32 -> 1 per warp) ----
    #pragma unroll
    for (int k = 4; k <= 8; k++) {
        const int m = 16384 >> (k + 1);           // per-row output length
        const int ml = 32 >> (k - 3);             // active lanes after this level
        float e = __shfl_sync(FULL, val, 2 * lane);
        float o = __shfl_sync(FULL, val, 2 * lane + 1);
        float a = (e - o) * S;
        val     = (e + o) * S;
        if (lane < ml) {
            size_t base = NR * (size_t)(16384 - (16384 >> k));
            __stcs(out + base + (size_t)row * m + w * ml + lane, a);
        }
    }
    // val at lane 0 of each warp = cD8[w]

    if (lane == 0) sm[w] = val;
    __syncthreads();

    // ---- levels 9..13 + final cD: warp 0 only ----
    if (w == 0) {
        val = sm[lane];   // 32 values: cD8[0..31]
        #pragma unroll
        for (int k = 9; k <= 13; k++) {
            const int m = 16384 >> (k + 1);       // 16,8,4,2,1
            float e = __shfl_sync(FULL, val, 2 * lane);
            float o = __shfl_sync(FULL, val, 2 * lane + 1);
            float a = (e - o) * S;
            val     = (e + o) * S;
            if (lane < m) {
                size_t base = NR * (size_t)(16384 - (16384 >> k));
                __stcs(out + base + (size_t)row * m + lane, a);
            }
        }
        if (lane == 0) {
            __stcs(out + NR * (size_t)16383 + row, val);   // final cD
        }
    }
}

extern "C" void kernel_launch(void* const* d_in, const int* in_sizes, int n_in,
                              void* d_out, int out_size)
{
    const float* x = (const float*)d_in[0];
    float* out = (float*)d_out;
    int n = in_sizes[0];
    int nrows = n / ROW_LEN;   // 4096 for (64,64,16384)
    haar14_kernel<<<nrows, THREADS>>>(x, out, nrows);
}